// round 3
// baseline (speedup 1.0000x reference)
#include <cuda_runtime.h>
#include <cstdint>

#define NN 50000
#define NE 800000
#define D  256
#define BN_EPS 1e-5f

// ---------------- scratch (static device allocations) ----------------
__device__ float g_h[NN * D];        // 51.2 MB: h = x @ W^T
__device__ float g_dinv[NN];
__device__ int   g_cnt[NN];          // in-degree (edges only)
__device__ int   g_cur[NN];          // fill cursors
__device__ int   g_off[NN + 1];      // CSR offsets by target
__device__ int   g_src[NE];          // CSR: source node per slot
__device__ float g_colsum[D];
__device__ float g_colsumsq[D];
__device__ float g_bn_a[D];
__device__ float g_bn_b[D];

// ---------------- zero counters ----------------
__global__ void k_zero(void) {
    int i = blockIdx.x * blockDim.x + threadIdx.x;
    if (i < NN) { g_cnt[i] = 0; g_cur[i] = 0; }
    if (i < D) { g_colsum[i] = 0.0f; g_colsumsq[i] = 0.0f; }
}

// ---------------- count edges per target (edge_index is int32!) ----------------
__global__ void k_count(const int* __restrict__ ei) {
    int e = blockIdx.x * blockDim.x + threadIdx.x;
    if (e < NE) atomicAdd(&g_cnt[ei[NE + e]], 1);
}

// ---------------- dinv = rsqrt(deg), deg = cnt + 1 (self loop) ----------------
__global__ void k_dinv(void) {
    int i = blockIdx.x * blockDim.x + threadIdx.x;
    if (i < NN) g_dinv[i] = rsqrtf((float)(g_cnt[i] + 1));
}

// ---------------- exclusive scan over g_cnt -> g_off (single block) ----------------
__global__ __launch_bounds__(1024) void k_scan(void) {
    __shared__ int s[1024];
    const int t = threadIdx.x;
    const int CH = (NN + 1023) / 1024;   // 49
    const int base = t * CH;
    int sum = 0;
    for (int i = 0; i < CH; i++) {
        int idx = base + i;
        if (idx < NN) sum += g_cnt[idx];
    }
    s[t] = sum;
    __syncthreads();
    // Hillis-Steele inclusive scan
    for (int off = 1; off < 1024; off <<= 1) {
        int v = (t >= off) ? s[t - off] : 0;
        __syncthreads();
        if (t >= off) s[t] += v;
        __syncthreads();
    }
    int run = (t == 0) ? 0 : s[t - 1];
    for (int i = 0; i < CH; i++) {
        int idx = base + i;
        if (idx < NN) {
            g_off[idx] = run;
            run += g_cnt[idx];
        }
    }
    if (t == 1023) g_off[NN] = run;
}

// ---------------- fill CSR ----------------
__global__ void k_fill(const int* __restrict__ ei) {
    int e = blockIdx.x * blockDim.x + threadIdx.x;
    if (e < NE) {
        int r = ei[e];
        int c = ei[NE + e];
        int pos = g_off[c] + atomicAdd(&g_cur[c], 1);
        g_src[pos] = r;
    }
}

// ---------------- GEMM: H[M,D] = X[M,D] * W[D,D]^T ----------------
// BM=128, BN=64, BK=16, 256 threads, 8x4 register tile per thread.
__global__ __launch_bounds__(256) void k_gemm(const float* __restrict__ X,
                                              const float* __restrict__ W,
                                              float* __restrict__ H) {
    __shared__ float As[16][128];
    __shared__ float Bs[16][64];
    const int bm = blockIdx.x * 128;
    const int bn = blockIdx.y * 64;
    const int tid = threadIdx.x;
    const int ty = tid >> 4;
    const int tx = tid & 15;

    float acc[8][4];
#pragma unroll
    for (int i = 0; i < 8; i++)
#pragma unroll
        for (int j = 0; j < 4; j++) acc[i][j] = 0.0f;

    for (int k0 = 0; k0 < D; k0 += 16) {
#pragma unroll
        for (int l = 0; l < 2; l++) {
            int f = tid + l * 256;
            int row = f >> 2;
            int kq = (f & 3) * 4;
            int gr = bm + row;
            float4 v = make_float4(0.f, 0.f, 0.f, 0.f);
            if (gr < NN) v = *(const float4*)&X[(size_t)gr * D + k0 + kq];
            As[kq + 0][row] = v.x;
            As[kq + 1][row] = v.y;
            As[kq + 2][row] = v.z;
            As[kq + 3][row] = v.w;
        }
        {
            int row = tid >> 2;
            int kq = (tid & 3) * 4;
            float4 v = *(const float4*)&W[(size_t)(bn + row) * D + k0 + kq];
            Bs[kq + 0][row] = v.x;
            Bs[kq + 1][row] = v.y;
            Bs[kq + 2][row] = v.z;
            Bs[kq + 3][row] = v.w;
        }
        __syncthreads();
#pragma unroll
        for (int kk = 0; kk < 16; kk++) {
            float a[8], b[4];
            *(float4*)&a[0] = *(const float4*)&As[kk][ty * 8];
            *(float4*)&a[4] = *(const float4*)&As[kk][ty * 8 + 4];
            *(float4*)&b[0] = *(const float4*)&Bs[kk][tx * 4];
#pragma unroll
            for (int i = 0; i < 8; i++)
#pragma unroll
                for (int j = 0; j < 4; j++) acc[i][j] = fmaf(a[i], b[j], acc[i][j]);
        }
        __syncthreads();
    }
#pragma unroll
    for (int i = 0; i < 8; i++) {
        int gr = bm + ty * 8 + i;
        if (gr < NN) {
            float4 v = make_float4(acc[i][0], acc[i][1], acc[i][2], acc[i][3]);
            *(float4*)&H[(size_t)gr * D + bn + tx * 4] = v;
        }
    }
}

// ---------------- gather: one block (256 thr) per target node ----------------
// out[c][d] = ( h[c][d]*dinv[c] + sum_j h[src_j][d]*dinv[src_j] ) * dinv[c] + bias[d]
__global__ __launch_bounds__(256) void k_gather(const float* __restrict__ bias,
                                                float* __restrict__ out) {
    const int c = blockIdx.x;
    const int d = threadIdx.x;
    const float dc = g_dinv[c];
    const int beg = g_off[c];
    const int end = g_off[c + 1];
    float acc = g_h[(size_t)c * D + d] * dc;   // self loop
    int j = beg;
    // 2-way unroll for MLP
    for (; j + 1 < end; j += 2) {
        int r0 = __ldg(&g_src[j]);
        int r1 = __ldg(&g_src[j + 1]);
        float w0 = g_dinv[r0];
        float w1 = g_dinv[r1];
        float v0 = g_h[(size_t)r0 * D + d];
        float v1 = g_h[(size_t)r1 * D + d];
        acc = fmaf(v0, w0, acc);
        acc = fmaf(v1, w1, acc);
    }
    if (j < end) {
        int r = __ldg(&g_src[j]);
        acc = fmaf(g_h[(size_t)r * D + d], g_dinv[r], acc);
    }
    out[(size_t)c * D + d] = fmaf(acc, dc, bias[d]);
}

// ---------------- BN stats ----------------
__global__ __launch_bounds__(256) void k_bn_stats(const float* __restrict__ out) {
    int d = threadIdx.x;
    float s = 0.f, s2 = 0.f;
    for (int row = blockIdx.x; row < NN; row += gridDim.x) {
        float v = out[(size_t)row * D + d];
        s += v;
        s2 = fmaf(v, v, s2);
    }
    atomicAdd(&g_colsum[d], s);
    atomicAdd(&g_colsumsq[d], s2);
}

__global__ void k_bn_params(const float* __restrict__ gamma, const float* __restrict__ beta) {
    int d = threadIdx.x;
    float inv_n = 1.0f / (float)NN;
    float mean = g_colsum[d] * inv_n;
    float var = g_colsumsq[d] * inv_n - mean * mean;
    float a = gamma[d] * rsqrtf(var + BN_EPS);
    g_bn_a[d] = a;
    g_bn_b[d] = beta[d] - mean * a;
}

__global__ void k_bn_apply(float* __restrict__ out) {
    int idx = blockIdx.x * blockDim.x + threadIdx.x;  // float4 index
    if (idx >= NN * (D / 4)) return;
    int dq = (idx & 63) * 4;
    float4 a = *(const float4*)&g_bn_a[dq];
    float4 b = *(const float4*)&g_bn_b[dq];
    float4 v = ((const float4*)out)[idx];
    float4 o;
    o.x = fmaxf(fmaf(v.x, a.x, b.x), 0.f);
    o.y = fmaxf(fmaf(v.y, a.y, b.y), 0.f);
    o.z = fmaxf(fmaf(v.z, a.z, b.z), 0.f);
    o.w = fmaxf(fmaf(v.w, a.w, b.w), 0.f);
    ((float4*)out)[idx] = o;
}

// ---------------- launch ----------------
extern "C" void kernel_launch(void* const* d_in, const int* in_sizes, int n_in,
                              void* d_out, int out_size) {
    const float* x = (const float*)d_in[0];
    const int* ei = (const int*)d_in[1];           // int32 (JAX x64 disabled)
    const float* W = (const float*)d_in[2];
    const float* bias = (const float*)d_in[3];
    const float* gamma = (const float*)d_in[4];
    const float* beta = (const float*)d_in[5];
    float* out = (float*)d_out;

    float* h;
    cudaGetSymbolAddress((void**)&h, g_h);

    k_zero<<<(NN + 255) / 256, 256>>>();
    k_count<<<(NE + 255) / 256, 256>>>(ei);
    k_dinv<<<(NN + 255) / 256, 256>>>();
    k_scan<<<1, 1024>>>();
    k_fill<<<(NE + 255) / 256, 256>>>(ei);

    dim3 ggrid((NN + 127) / 128, D / 64);
    k_gemm<<<ggrid, 256>>>(x, W, h);

    k_gather<<<NN, 256>>>(bias, out);

    k_bn_stats<<<512, 256>>>(out);
    k_bn_params<<<1, 256>>>(gamma, beta);

    int q = NN * (D / 4);
    k_bn_apply<<<(q + 255) / 256, 256>>>(out);
}

// round 4
// speedup vs baseline: 1.2687x; 1.2687x over previous
#include <cuda_runtime.h>
#include <cstdint>

#define NN 50000
#define NE 800000
#define D  256
#define BN_EPS 1e-5f
#define NSCB 196   // ceil(NN/256) scan blocks

// ---------------- scratch (static device allocations) ----------------
__device__ float g_h[NN * D];        // 51.2 MB: h = x @ W^T
__device__ float g_dinv[NN];
__device__ int   g_cnt[NN];
__device__ int   g_cur[NN];
__device__ int   g_off[NN + 1];
__device__ int   g_src[NE];
__device__ int   g_bsum[NSCB];
__device__ int   g_boff[NSCB];
__device__ float g_colsum[D];
__device__ float g_colsumsq[D];
__device__ float g_bn_a[D];
__device__ float g_bn_b[D];

// ---------------- zero counters ----------------
__global__ void k_zero(void) {
    int i = blockIdx.x * blockDim.x + threadIdx.x;
    if (i < NN) { g_cnt[i] = 0; g_cur[i] = 0; }
    if (i < D) { g_colsum[i] = 0.0f; g_colsumsq[i] = 0.0f; }
}

__global__ void k_count(const int* __restrict__ ei) {
    int e = blockIdx.x * blockDim.x + threadIdx.x;
    if (e < NE) atomicAdd(&g_cnt[ei[NE + e]], 1);
}

__global__ void k_dinv(void) {
    int i = blockIdx.x * blockDim.x + threadIdx.x;
    if (i < NN) g_dinv[i] = rsqrtf((float)(g_cnt[i] + 1));
}

// ---------------- multi-block exclusive scan ----------------
__device__ __forceinline__ int block_incl_scan256(int v, int tid) {
    __shared__ int ws[8];
    int lane = tid & 31, w = tid >> 5;
    int inc = v;
#pragma unroll
    for (int o = 1; o < 32; o <<= 1) {
        int n = __shfl_up_sync(0xFFFFFFFFu, inc, o);
        if (lane >= o) inc += n;
    }
    if (lane == 31) ws[w] = inc;
    __syncthreads();
    if (w == 0) {
        int s = (lane < 8) ? ws[lane] : 0;
#pragma unroll
        for (int o = 1; o < 8; o <<= 1) {
            int n = __shfl_up_sync(0xFFFFFFFFu, s, o);
            if (lane >= o) s += n;
        }
        if (lane < 8) ws[lane] = s;
    }
    __syncthreads();
    return inc + (w > 0 ? ws[w - 1] : 0);
}

__global__ __launch_bounds__(256) void k_scan1(void) {
    int tid = threadIdx.x;
    int idx = blockIdx.x * 256 + tid;
    int v = (idx < NN) ? g_cnt[idx] : 0;
    int inc = block_incl_scan256(v, tid);
    if (idx < NN) g_off[idx] = inc - v;       // local exclusive
    if (tid == 255) g_bsum[blockIdx.x] = inc; // block total
}

__global__ __launch_bounds__(256) void k_scan2(void) {
    int tid = threadIdx.x;
    int v = (tid < NSCB) ? g_bsum[tid] : 0;
    int inc = block_incl_scan256(v, tid);
    if (tid < NSCB) g_boff[tid] = inc - v;    // exclusive block offset
}

__global__ __launch_bounds__(256) void k_scan3(void) {
    int tid = threadIdx.x;
    int idx = blockIdx.x * 256 + tid;
    if (idx < NN) g_off[idx] += g_boff[blockIdx.x];
    if (idx == 0) g_off[NN] = NE;
}

__global__ void k_fill(const int* __restrict__ ei) {
    int e = blockIdx.x * blockDim.x + threadIdx.x;
    if (e < NE) {
        int r = ei[e];
        int c = ei[NE + e];
        int pos = g_off[c] + atomicAdd(&g_cur[c], 1);
        g_src[pos] = r;
    }
}

// ---------------- 3xTF32 tensor-core GEMM: H = X @ W^T ----------------
// BM=128 BN=64 BK=16, 256 threads = 8 warps (4 m-dir x 2 n-dir), warp tile 32x32.
// mma.sync.aligned.m16n8k8.row.col.f32.tf32.tf32.f32
#define GPAD 20   // padded smem k-stride (floats): 80B rows, 16B aligned, conflict-free frags

__device__ __forceinline__ unsigned f2tf32(float f) {
    unsigned r;
    asm("cvt.rna.tf32.f32 %0, %1;" : "=r"(r) : "f"(f));
    return r;
}

#define MMA_TF32(acc, a, b) \
    asm volatile("mma.sync.aligned.m16n8k8.row.col.f32.tf32.tf32.f32 " \
                 "{%0,%1,%2,%3},{%4,%5,%6,%7},{%8,%9},{%0,%1,%2,%3};" \
                 : "+f"(acc[0]), "+f"(acc[1]), "+f"(acc[2]), "+f"(acc[3]) \
                 : "r"(a[0]), "r"(a[1]), "r"(a[2]), "r"(a[3]), "r"(b[0]), "r"(b[1]))

__global__ __launch_bounds__(256) void k_gemm_tf32(const float* __restrict__ X,
                                                   const float* __restrict__ W,
                                                   float* __restrict__ H) {
    __shared__ unsigned Ahi[128][GPAD], Alo[128][GPAD];
    __shared__ unsigned Bhi[64][GPAD],  Blo[64][GPAD];

    const int bm = blockIdx.x * 128;
    const int bn = blockIdx.y * 64;
    const int tid = threadIdx.x;
    const int warp = tid >> 5, lane = tid & 31;
    const int wm = warp & 3, wn = warp >> 2;   // warp origin (wm*32, wn*32)
    const int grp = lane >> 2, tig = lane & 3;

    float acc[2][4][4];
#pragma unroll
    for (int mi = 0; mi < 2; mi++)
#pragma unroll
        for (int ni = 0; ni < 4; ni++)
#pragma unroll
            for (int q = 0; q < 4; q++) acc[mi][ni][q] = 0.0f;

    for (int k0 = 0; k0 < D; k0 += 16) {
        // A tile: 128 rows x 16 k = 512 float4 loads, 2 per thread
#pragma unroll
        for (int p = 0; p < 2; p++) {
            int f = tid + p * 256;
            int row = f >> 2;
            int kq = (f & 3) * 4;
            float4 v = make_float4(0.f, 0.f, 0.f, 0.f);
            int gr = bm + row;
            if (gr < NN) v = *(const float4*)&X[(size_t)gr * D + k0 + kq];
            unsigned h0 = f2tf32(v.x), h1 = f2tf32(v.y), h2 = f2tf32(v.z), h3 = f2tf32(v.w);
            Ahi[row][kq+0] = h0; Ahi[row][kq+1] = h1; Ahi[row][kq+2] = h2; Ahi[row][kq+3] = h3;
            Alo[row][kq+0] = f2tf32(v.x - __uint_as_float(h0));
            Alo[row][kq+1] = f2tf32(v.y - __uint_as_float(h1));
            Alo[row][kq+2] = f2tf32(v.z - __uint_as_float(h2));
            Alo[row][kq+3] = f2tf32(v.w - __uint_as_float(h3));
        }
        // B tile: 64 rows x 16 k = 256 float4 loads, 1 per thread
        {
            int row = tid >> 2;
            int kq = (tid & 3) * 4;
            float4 v = *(const float4*)&W[(size_t)(bn + row) * D + k0 + kq];
            unsigned h0 = f2tf32(v.x), h1 = f2tf32(v.y), h2 = f2tf32(v.z), h3 = f2tf32(v.w);
            Bhi[row][kq+0] = h0; Bhi[row][kq+1] = h1; Bhi[row][kq+2] = h2; Bhi[row][kq+3] = h3;
            Blo[row][kq+0] = f2tf32(v.x - __uint_as_float(h0));
            Blo[row][kq+1] = f2tf32(v.y - __uint_as_float(h1));
            Blo[row][kq+2] = f2tf32(v.z - __uint_as_float(h2));
            Blo[row][kq+3] = f2tf32(v.w - __uint_as_float(h3));
        }
        __syncthreads();

#pragma unroll
        for (int ks = 0; ks < 16; ks += 8) {
            unsigned ah[2][4], al[2][4], bh[4][2], bl[4][2];
#pragma unroll
            for (int mi = 0; mi < 2; mi++) {
                int r = wm * 32 + mi * 16 + grp;
                ah[mi][0] = Ahi[r][ks+tig];     ah[mi][1] = Ahi[r+8][ks+tig];
                ah[mi][2] = Ahi[r][ks+tig+4];   ah[mi][3] = Ahi[r+8][ks+tig+4];
                al[mi][0] = Alo[r][ks+tig];     al[mi][1] = Alo[r+8][ks+tig];
                al[mi][2] = Alo[r][ks+tig+4];   al[mi][3] = Alo[r+8][ks+tig+4];
            }
#pragma unroll
            for (int ni = 0; ni < 4; ni++) {
                int c = wn * 32 + ni * 8 + grp;
                bh[ni][0] = Bhi[c][ks+tig];  bh[ni][1] = Bhi[c][ks+tig+4];
                bl[ni][0] = Blo[c][ks+tig];  bl[ni][1] = Blo[c][ks+tig+4];
            }
#pragma unroll
            for (int mi = 0; mi < 2; mi++)
#pragma unroll
                for (int ni = 0; ni < 4; ni++) {
                    MMA_TF32(acc[mi][ni], ah[mi], bh[ni]);
                    MMA_TF32(acc[mi][ni], ah[mi], bl[ni]);
                    MMA_TF32(acc[mi][ni], al[mi], bh[ni]);
                }
        }
        __syncthreads();
    }

    // store C: c0,c1 at (r, c), (r, c+1); c2,c3 at (r+8, ...)
#pragma unroll
    for (int mi = 0; mi < 2; mi++)
#pragma unroll
        for (int ni = 0; ni < 4; ni++) {
            int r0 = bm + wm * 32 + mi * 16 + grp;
            int c0 = bn + wn * 32 + ni * 8 + tig * 2;
            if (r0 < NN) {
                float2 v = make_float2(acc[mi][ni][0], acc[mi][ni][1]);
                *(float2*)&H[(size_t)r0 * D + c0] = v;
            }
            if (r0 + 8 < NN) {
                float2 v = make_float2(acc[mi][ni][2], acc[mi][ni][3]);
                *(float2*)&H[(size_t)(r0 + 8) * D + c0] = v;
            }
        }
}

// ---------------- gather: one block (256 thr) per target node ----------------
__global__ __launch_bounds__(256) void k_gather(const float* __restrict__ bias,
                                                float* __restrict__ out) {
    const int c = blockIdx.x;
    const int d = threadIdx.x;
    const float dc = g_dinv[c];
    const int beg = g_off[c];
    const int end = g_off[c + 1];
    float acc = g_h[(size_t)c * D + d] * dc;   // self loop
    int j = beg;
    for (; j + 1 < end; j += 2) {
        int r0 = __ldg(&g_src[j]);
        int r1 = __ldg(&g_src[j + 1]);
        float w0 = g_dinv[r0];
        float w1 = g_dinv[r1];
        float v0 = g_h[(size_t)r0 * D + d];
        float v1 = g_h[(size_t)r1 * D + d];
        acc = fmaf(v0, w0, acc);
        acc = fmaf(v1, w1, acc);
    }
    if (j < end) {
        int r = __ldg(&g_src[j]);
        acc = fmaf(g_h[(size_t)r * D + d], g_dinv[r], acc);
    }
    out[(size_t)c * D + d] = fmaf(acc, dc, bias[d]);
}

// ---------------- BN ----------------
__global__ __launch_bounds__(256) void k_bn_stats(const float* __restrict__ out) {
    int d = threadIdx.x;
    float s = 0.f, s2 = 0.f;
    for (int row = blockIdx.x; row < NN; row += gridDim.x) {
        float v = out[(size_t)row * D + d];
        s += v;
        s2 = fmaf(v, v, s2);
    }
    atomicAdd(&g_colsum[d], s);
    atomicAdd(&g_colsumsq[d], s2);
}

__global__ void k_bn_params(const float* __restrict__ gamma, const float* __restrict__ beta) {
    int d = threadIdx.x;
    float inv_n = 1.0f / (float)NN;
    float mean = g_colsum[d] * inv_n;
    float var = g_colsumsq[d] * inv_n - mean * mean;
    float a = gamma[d] * rsqrtf(var + BN_EPS);
    g_bn_a[d] = a;
    g_bn_b[d] = beta[d] - mean * a;
}

__global__ void k_bn_apply(float* __restrict__ out) {
    int idx = blockIdx.x * blockDim.x + threadIdx.x;
    if (idx >= NN * (D / 4)) return;
    int dq = (idx & 63) * 4;
    float4 a = *(const float4*)&g_bn_a[dq];
    float4 b = *(const float4*)&g_bn_b[dq];
    float4 v = ((const float4*)out)[idx];
    float4 o;
    o.x = fmaxf(fmaf(v.x, a.x, b.x), 0.f);
    o.y = fmaxf(fmaf(v.y, a.y, b.y), 0.f);
    o.z = fmaxf(fmaf(v.z, a.z, b.z), 0.f);
    o.w = fmaxf(fmaf(v.w, a.w, b.w), 0.f);
    ((float4*)out)[idx] = o;
}

// ---------------- launch ----------------
extern "C" void kernel_launch(void* const* d_in, const int* in_sizes, int n_in,
                              void* d_out, int out_size) {
    const float* x = (const float*)d_in[0];
    const int* ei = (const int*)d_in[1];
    const float* W = (const float*)d_in[2];
    const float* bias = (const float*)d_in[3];
    const float* gamma = (const float*)d_in[4];
    const float* beta = (const float*)d_in[5];
    float* out = (float*)d_out;

    float* h;
    cudaGetSymbolAddress((void**)&h, g_h);

    k_zero<<<(NN + 255) / 256, 256>>>();
    k_count<<<(NE + 255) / 256, 256>>>(ei);
    k_dinv<<<(NN + 255) / 256, 256>>>();
    k_scan1<<<NSCB, 256>>>();
    k_scan2<<<1, 256>>>();
    k_scan3<<<NSCB, 256>>>();
    k_fill<<<(NE + 255) / 256, 256>>>(ei);

    dim3 ggrid((NN + 127) / 128, D / 64);
    k_gemm_tf32<<<ggrid, 256>>>(x, W, h);

    k_gather<<<NN, 256>>>(bias, out);

    k_bn_stats<<<512, 256>>>(out);
    k_bn_params<<<1, 256>>>(gamma, beta);

    int q = NN * (D / 4);
    k_bn_apply<<<(q + 255) / 256, 256>>>(out);
}